// round 1
// baseline (speedup 1.0000x reference)
#include <cuda_runtime.h>
#include <cuda_bf16.h>
#include <math.h>

#define D_MODEL 1280
#define NHEADS  16
#define HDIM    80
#define S_MAX   4096

// ---------------- scratch (device globals; no allocation allowed) ----------
__device__ float g_qkv[S_MAX * 3 * D_MODEL];          // (S, 3*D)
__device__ float g_q[NHEADS * S_MAX * HDIM];          // (H, S, hd) roped
__device__ float g_k[NHEADS * S_MAX * HDIM];          // (H, S, hd) roped
__device__ float g_v[NHEADS * S_MAX * HDIM];          // (H, S, hd)
__device__ float g_attn[S_MAX * D_MODEL];             // (S, D) pre-proj

// ---------------- fp32 SGEMM: C = A(MxK) @ B(KxN) + bias -------------------
// 128x128 block, BK=8, 8x8 per thread, 256 threads.
#define BM 128
#define BN 128
#define BKK 8
#define TM 8
#define TN 8

__global__ __launch_bounds__(256, 2)
void sgemm_bias(int M, int N, int K,
                const float* __restrict__ A,
                const float* __restrict__ B,
                const float* __restrict__ bias,
                float* __restrict__ C)
{
    __shared__ float As[BKK * BM];   // transposed: As[k][m]
    __shared__ float Bs[BKK * BN];   // Bs[k][n]

    const int tid  = threadIdx.x;
    const int brow = blockIdx.y;
    const int bcol = blockIdx.x;

    A += (size_t)brow * BM * K;
    B += (size_t)bcol * BN;
    C += (size_t)brow * BM * N + (size_t)bcol * BN;

    const int innerRowA = tid >> 1;            // 0..127
    const int innerColA = (tid & 1) * 4;       // 0 or 4
    const int innerRowB = tid >> 5;            // 0..7
    const int innerColB = (tid & 31) * 4;      // 0..124
    const int threadRow = (tid >> 4) * TM;     // 0..120
    const int threadCol = (tid & 15) * TN;     // 0..120

    float acc[TM][TN];
    #pragma unroll
    for (int i = 0; i < TM; i++)
        #pragma unroll
        for (int j = 0; j < TN; j++) acc[i][j] = 0.f;

    for (int k0 = 0; k0 < K; k0 += BKK) {
        float4 a = *reinterpret_cast<const float4*>(A + (size_t)innerRowA * K + k0 + innerColA);
        As[(innerColA + 0) * BM + innerRowA] = a.x;
        As[(innerColA + 1) * BM + innerRowA] = a.y;
        As[(innerColA + 2) * BM + innerRowA] = a.z;
        As[(innerColA + 3) * BM + innerRowA] = a.w;
        float4 b = *reinterpret_cast<const float4*>(B + (size_t)(k0 + innerRowB) * N + innerColB);
        *reinterpret_cast<float4*>(&Bs[innerRowB * BN + innerColB]) = b;
        __syncthreads();

        #pragma unroll
        for (int k = 0; k < BKK; k++) {
            float4 a0 = *reinterpret_cast<const float4*>(&As[k * BM + threadRow]);
            float4 a1 = *reinterpret_cast<const float4*>(&As[k * BM + threadRow + 4]);
            float4 b0 = *reinterpret_cast<const float4*>(&Bs[k * BN + threadCol]);
            float4 b1 = *reinterpret_cast<const float4*>(&Bs[k * BN + threadCol + 4]);
            float regM[TM] = {a0.x, a0.y, a0.z, a0.w, a1.x, a1.y, a1.z, a1.w};
            float regN[TN] = {b0.x, b0.y, b0.z, b0.w, b1.x, b1.y, b1.z, b1.w};
            #pragma unroll
            for (int i = 0; i < TM; i++)
                #pragma unroll
                for (int j = 0; j < TN; j++)
                    acc[i][j] += regM[i] * regN[j];
        }
        __syncthreads();
    }

    #pragma unroll
    for (int i = 0; i < TM; i++) {
        #pragma unroll
        for (int j = 0; j < TN; j += 4) {
            float4 v;
            v.x = acc[i][j + 0] + bias[bcol * BN + threadCol + j + 0];
            v.y = acc[i][j + 1] + bias[bcol * BN + threadCol + j + 1];
            v.z = acc[i][j + 2] + bias[bcol * BN + threadCol + j + 2];
            v.w = acc[i][j + 3] + bias[bcol * BN + threadCol + j + 3];
            *reinterpret_cast<float4*>(&C[(size_t)(threadRow + i) * N + threadCol + j]) = v;
        }
    }
}

// ---------------- RoPE + scatter to (H, S, hd) -----------------------------
__global__ void rope_scatter(const float* __restrict__ qkv,
                             const float* __restrict__ freqs,
                             float* __restrict__ Q,
                             float* __restrict__ K,
                             float* __restrict__ V,
                             int S)
{
    const int s = blockIdx.x;
    const float* base = qkv + (size_t)s * (3 * D_MODEL);
    for (int idx = threadIdx.x; idx < NHEADS * HDIM; idx += blockDim.x) {
        const int h = idx / HDIM;
        const int d = idx % HDIM;
        const int dd = (d < 40) ? d : d - 40;
        const float f  = freqs[(size_t)s * 40 + dd];
        const float cs = cosf(f), sn = sinf(f);
        const float q1 = base[h * HDIM + dd];
        const float q2 = base[h * HDIM + dd + 40];
        const float k1 = base[D_MODEL + h * HDIM + dd];
        const float k2 = base[D_MODEL + h * HDIM + dd + 40];
        const float qo = (d < 40) ? (q1 * cs - q2 * sn) : (q1 * sn + q2 * cs);
        const float ko = (d < 40) ? (k1 * cs - k2 * sn) : (k1 * sn + k2 * cs);
        const size_t o = ((size_t)h * S + s) * HDIM + d;
        Q[o] = qo;
        K[o] = ko;
        V[o] = base[2 * D_MODEL + h * HDIM + d];
    }
}

// ---------------- flash-style block-diagonal attention ---------------------
// block = (q-tile of 64, head). 256 threads. Online softmax over 64-wide kv tiles.
#define QT 64
#define KT 64
#define ATTN_SMEM_FLOATS (64*80 + 64*81 + 64*81 + 64*65 + 64 + 64)

__global__ __launch_bounds__(256, 2)
void attn_kernel(const float* __restrict__ Qg,
                 const float* __restrict__ Kg,
                 const float* __restrict__ Vg,
                 const int* __restrict__ cu,
                 int n_seg,
                 float* __restrict__ out,
                 int S)
{
    extern __shared__ float sm[];
    float* Qs      = sm;                 // 64 x 80
    float* Ks      = Qs + 64 * 80;       // 64 x 81 (padded)
    float* Vs      = Ks + 64 * 81;       // 64 x 81
    float* Ss      = Vs + 64 * 81;       // 64 x 65
    float* alpha_s = Ss + 64 * 65;       // 64
    float* l_s     = alpha_s + 64;       // 64

    const int tid = threadIdx.x;
    const int h   = blockIdx.y;
    const int q0  = blockIdx.x * QT;

    int start = 0, end = S;
    for (int i = 0; i < n_seg; i++) {
        int a = cu[i], b = cu[i + 1];
        if (a <= q0 && q0 < b) { start = a; end = b; }
    }

    const int ty  = tid >> 4;      // 0..15 (score/PV mapping)
    const int tx  = tid & 15;      // 0..15
    const int r4  = tid >> 2;      // 0..63 (softmax mapping)
    const int sub = tid & 3;       // 0..3

    // load Q tile (rows contiguous)
    {
        const float4* Qg4 = reinterpret_cast<const float4*>(Qg + ((size_t)h * S + q0) * HDIM);
        float4* Qs4 = reinterpret_cast<float4*>(Qs);
        for (int i = tid; i < 64 * 20; i += 256) Qs4[i] = Qg4[i];
    }

    float o[4][5];
    #pragma unroll
    for (int i = 0; i < 4; i++)
        #pragma unroll
        for (int j = 0; j < 5; j++) o[i][j] = 0.f;

    float m_run = -INFINITY, l_run = 0.f;
    const float scale = 0.11180339887498949f;   // 1/sqrt(80)

    const int nkt = (end - start + KT - 1) / KT;
    for (int t = 0; t < nkt; t++) {
        const int k0 = start + t * KT;
        __syncthreads();   // previous iteration's smem consumers are done

        // load K/V tiles into padded smem
        for (int i = tid; i < 64 * 20; i += 256) {
            const int r  = i / 20;
            const int c4 = (i % 20) * 4;
            float4 kk, vv;
            if (k0 + r < end) {
                kk = *reinterpret_cast<const float4*>(Kg + ((size_t)h * S + k0 + r) * HDIM + c4);
                vv = *reinterpret_cast<const float4*>(Vg + ((size_t)h * S + k0 + r) * HDIM + c4);
            } else {
                kk = make_float4(0.f, 0.f, 0.f, 0.f);
                vv = kk;
            }
            float* kd = Ks + r * 81 + c4;
            kd[0] = kk.x; kd[1] = kk.y; kd[2] = kk.z; kd[3] = kk.w;
            float* vd = Vs + r * 81 + c4;
            vd[0] = vv.x; vd[1] = vv.y; vd[2] = vv.z; vd[3] = vv.w;
        }
        __syncthreads();

        // scores: 4x4 per thread
        float acc[4][4];
        #pragma unroll
        for (int i = 0; i < 4; i++)
            #pragma unroll
            for (int j = 0; j < 4; j++) acc[i][j] = 0.f;

        #pragma unroll 4
        for (int d = 0; d < HDIM; d++) {
            float qreg[4], kreg[4];
            #pragma unroll
            for (int i = 0; i < 4; i++) qreg[i] = Qs[(ty * 4 + i) * 80 + d];
            #pragma unroll
            for (int j = 0; j < 4; j++) kreg[j] = Ks[(tx * 4 + j) * 81 + d];
            #pragma unroll
            for (int i = 0; i < 4; i++)
                #pragma unroll
                for (int j = 0; j < 4; j++)
                    acc[i][j] += qreg[i] * kreg[j];
        }
        const int nv = end - k0;  // valid key count in this tile
        #pragma unroll
        for (int i = 0; i < 4; i++)
            #pragma unroll
            for (int j = 0; j < 4; j++) {
                const int c = tx * 4 + j;
                Ss[(ty * 4 + i) * 65 + c] = (c < nv) ? acc[i][j] * scale : -1e30f;
            }
        __syncthreads();

        // online softmax (quad mapping: row r4, 16 cols per thread)
        float sv[16];
        float mt = -INFINITY;
        #pragma unroll
        for (int j = 0; j < 16; j++) {
            sv[j] = Ss[r4 * 65 + sub * 16 + j];
            mt = fmaxf(mt, sv[j]);
        }
        mt = fmaxf(mt, __shfl_xor_sync(0xffffffffu, mt, 1));
        mt = fmaxf(mt, __shfl_xor_sync(0xffffffffu, mt, 2));
        const float m_new = fmaxf(m_run, mt);
        const float al = __expf(m_run - m_new);
        float rs = 0.f;
        #pragma unroll
        for (int j = 0; j < 16; j++) {
            const float p = __expf(sv[j] - m_new);
            Ss[r4 * 65 + sub * 16 + j] = p;
            rs += p;
        }
        rs += __shfl_xor_sync(0xffffffffu, rs, 1);
        rs += __shfl_xor_sync(0xffffffffu, rs, 2);
        l_run = l_run * al + rs;
        m_run = m_new;
        if (sub == 0) alpha_s[r4] = al;
        __syncthreads();

        // PV: rescale + accumulate (4 rows x 5 dims per thread)
        #pragma unroll
        for (int i = 0; i < 4; i++) {
            const float ai = alpha_s[ty * 4 + i];
            #pragma unroll
            for (int j = 0; j < 5; j++) o[i][j] *= ai;
        }
        #pragma unroll 4
        for (int c = 0; c < KT; c++) {
            float pv[4], vv[5];
            #pragma unroll
            for (int i = 0; i < 4; i++) pv[i] = Ss[(ty * 4 + i) * 65 + c];
            #pragma unroll
            for (int j = 0; j < 5; j++) vv[j] = Vs[c * 81 + tx * 5 + j];
            #pragma unroll
            for (int i = 0; i < 4; i++)
                #pragma unroll
                for (int j = 0; j < 5; j++)
                    o[i][j] += pv[i] * vv[j];
        }
    }

    if (sub == 0) l_s[r4] = l_run;
    __syncthreads();

    #pragma unroll
    for (int i = 0; i < 4; i++) {
        const int row = q0 + ty * 4 + i;
        if (row < end) {
            const float inv = 1.f / l_s[ty * 4 + i];
            #pragma unroll
            for (int j = 0; j < 5; j++)
                out[(size_t)row * D_MODEL + h * HDIM + tx * 5 + j] = o[i][j] * inv;
        }
    }
}

// ---------------- launch ----------------------------------------------------
extern "C" void kernel_launch(void* const* d_in, const int* in_sizes, int n_in,
                              void* d_out, int out_size)
{
    const float* hidden = (const float*)d_in[0];
    const int*   cu     = (const int*)  d_in[1];
    const float* rope   = (const float*)d_in[2];
    const float* w_qkv  = (const float*)d_in[3];
    const float* b_qkv  = (const float*)d_in[4];
    const float* w_proj = (const float*)d_in[5];
    const float* b_proj = (const float*)d_in[6];
    float* out = (float*)d_out;

    const int S     = in_sizes[0] / D_MODEL;     // 4096
    const int n_seg = in_sizes[1] - 1;           // 4

    float *qkv_p, *q_p, *k_p, *v_p, *attn_p;
    cudaGetSymbolAddress((void**)&qkv_p,  g_qkv);
    cudaGetSymbolAddress((void**)&q_p,    g_q);
    cudaGetSymbolAddress((void**)&k_p,    g_k);
    cudaGetSymbolAddress((void**)&v_p,    g_v);
    cudaGetSymbolAddress((void**)&attn_p, g_attn);

    // 1) QKV projection: (S, D) @ (D, 3D) + b
    {
        dim3 grid((3 * D_MODEL) / BN, S / BM);
        sgemm_bias<<<grid, 256>>>(S, 3 * D_MODEL, D_MODEL, hidden, w_qkv, b_qkv, qkv_p);
    }

    // 2) RoPE + scatter to (H, S, hd)
    rope_scatter<<<S, 256>>>(qkv_p, rope, q_p, k_p, v_p, S);

    // 3) block-diagonal attention
    {
        const size_t smem = ATTN_SMEM_FLOATS * sizeof(float);
        cudaFuncSetAttribute(attn_kernel, cudaFuncAttributeMaxDynamicSharedMemorySize, (int)smem);
        dim3 grid(S / QT, NHEADS);
        attn_kernel<<<grid, 256, smem>>>(q_p, k_p, v_p, cu, n_seg, attn_p, S);
    }

    // 4) output projection: (S, D) @ (D, D) + b
    {
        dim3 grid(D_MODEL / BN, S / BM);
        sgemm_bias<<<grid, 256>>>(S, D_MODEL, D_MODEL, attn_p, w_proj, b_proj, out);
    }
}

// round 3
// speedup vs baseline: 1.8021x; 1.8021x over previous
#include <cuda_runtime.h>
#include <math.h>
#include <cstdint>

#define D_MODEL 1280
#define NHEADS  16
#define HDIM    80
#define S_MAX   4096

// ---------------- scratch (device globals; no allocation allowed) ----------
__device__ float g_qkv[S_MAX * 3 * D_MODEL];
__device__ float g_q[NHEADS * S_MAX * HDIM];
__device__ float g_k[NHEADS * S_MAX * HDIM];
__device__ float g_v[NHEADS * S_MAX * HDIM];
__device__ float g_attn[S_MAX * D_MODEL];
__device__ float g_wqkv_t[3 * D_MODEL * D_MODEL];   // (3D, D) K-major
__device__ float g_wproj_t[D_MODEL * D_MODEL];      // (D, D) K-major

// ======================= helpers ===========================================
__device__ __forceinline__ uint32_t smem_u32(const void* p) {
    uint32_t a;
    asm("{ .reg .u64 t; cvta.to.shared.u64 t, %1; cvt.u32.u64 %0, t; }" : "=r"(a) : "l"(p));
    return a;
}
__device__ __forceinline__ void cp16(uint32_t dst, const void* src) {
    asm volatile("cp.async.cg.shared.global [%0], [%1], 16;" :: "r"(dst), "l"(src));
}
#define CP_COMMIT() asm volatile("cp.async.commit_group;" ::: "memory")
#define CP_WAIT(n)  asm volatile("cp.async.wait_group %0;" :: "n"(n) : "memory")

__device__ __forceinline__ uint32_t f2tf32(float x) {
    uint32_t r;
    asm("cvt.rna.tf32.f32 %0, %1;" : "=r"(r) : "f"(x));
    return r;
}
__device__ __forceinline__ void mma_tf32(float* c, const uint32_t* a, const uint32_t* b) {
    asm volatile(
        "mma.sync.aligned.m16n8k8.row.col.f32.tf32.tf32.f32 "
        "{%0,%1,%2,%3}, {%4,%5,%6,%7}, {%8,%9}, {%0,%1,%2,%3};"
        : "+f"(c[0]), "+f"(c[1]), "+f"(c[2]), "+f"(c[3])
        : "r"(a[0]), "r"(a[1]), "r"(a[2]), "r"(a[3]), "r"(b[0]), "r"(b[1]));
}

// ======================= transpose (K,N) -> (N,K) ==========================
__global__ void transpose_kernel(const float* __restrict__ in, float* __restrict__ out,
                                 int K, int N) {
    __shared__ float tile[32][33];
    const int k0 = blockIdx.y * 32, n0 = blockIdx.x * 32;
    const int tx = threadIdx.x, ty = threadIdx.y;
    #pragma unroll
    for (int i = ty; i < 32; i += 8)
        tile[i][tx] = in[(size_t)(k0 + i) * N + n0 + tx];
    __syncthreads();
    #pragma unroll
    for (int i = ty; i < 32; i += 8)
        out[(size_t)(n0 + i) * K + k0 + tx] = tile[tx][i];
}

// ======================= tf32 mma.sync GEMM ================================
// C(MxN) = A(MxK) @ Bt(NxK)^T + bias. 128x128 tile, BK=32, double-buffered
// cp.async. 8 warps, warp tile 32(M) x 64(N), m16n8k8 tf32 HMMA.
#define GSTR 36                       // smem row stride (floats), conflict-free
#define GEMM_SMEM (2 * 2 * 128 * GSTR * 4)   // 73728 bytes

__global__ __launch_bounds__(256, 1)
void gemm_tf32(const float* __restrict__ A, const float* __restrict__ Bt,
               const float* __restrict__ bias, float* __restrict__ C,
               int M, int N, int K)
{
    extern __shared__ float sm[];
    const int tid  = threadIdx.x;
    const int warp = tid >> 5, lane = tid & 31;
    const int gid  = lane >> 2, tid4 = lane & 3;
    const int wm0  = (warp & 3) * 32;
    const int wn0  = (warp >> 2) * 64;
    const int bx = blockIdx.x, by = blockIdx.y;

    const float* Ablk = A  + (size_t)by * 128 * K;
    const float* Bblk = Bt + (size_t)bx * 128 * K;
    const int NS = K / 32;
    const uint32_t sbase = smem_u32(sm);

    // one stage = A tile (128x32) + B tile (128x32), each row padded to GSTR
    auto load_stage = [&](int b, int ks) {
        #pragma unroll
        for (int i = 0; i < 8; i++) {
            const int id  = tid + i * 256;
            const int isB = id >> 10;
            const int row = (id >> 3) & 127;
            const int c16 = id & 7;
            const float* src = (isB ? Bblk : Ablk) + (size_t)row * K + ks * 32 + c16 * 4;
            const uint32_t dst = sbase +
                (uint32_t)(b * (2 * 128 * GSTR) + isB * (128 * GSTR) + row * GSTR + c16 * 4) * 4u;
            cp16(dst, src);
        }
        CP_COMMIT();
    };

    float acc[2][8][4];
    #pragma unroll
    for (int mt = 0; mt < 2; mt++)
        #pragma unroll
        for (int nt = 0; nt < 8; nt++)
            #pragma unroll
            for (int r = 0; r < 4; r++) acc[mt][nt][r] = 0.f;

    load_stage(0, 0);
    for (int ks = 0; ks < NS; ks++) {
        const int b = ks & 1;
        if (ks + 1 < NS) { load_stage(1 - b, ks + 1); CP_WAIT(1); }
        else             { CP_WAIT(0); }
        __syncthreads();

        const float* As = sm + b * (2 * 128 * GSTR);
        const float* Bs = As + 128 * GSTR;

        #pragma unroll
        for (int kk = 0; kk < 4; kk++) {
            const int k0 = kk * 8;
            uint32_t af[2][4], bf[8][2];
            #pragma unroll
            for (int mt = 0; mt < 2; mt++) {
                const int r = (wm0 + mt * 16 + gid) * GSTR;
                af[mt][0] = f2tf32(As[r + k0 + tid4]);
                af[mt][1] = f2tf32(As[r + 8 * GSTR + k0 + tid4]);
                af[mt][2] = f2tf32(As[r + k0 + tid4 + 4]);
                af[mt][3] = f2tf32(As[r + 8 * GSTR + k0 + tid4 + 4]);
            }
            #pragma unroll
            for (int nt = 0; nt < 8; nt++) {
                const int r = (wn0 + nt * 8 + gid) * GSTR;
                bf[nt][0] = f2tf32(Bs[r + k0 + tid4]);
                bf[nt][1] = f2tf32(Bs[r + k0 + tid4 + 4]);
            }
            #pragma unroll
            for (int mt = 0; mt < 2; mt++)
                #pragma unroll
                for (int nt = 0; nt < 8; nt++)
                    mma_tf32(acc[mt][nt], af[mt], bf[nt]);
        }
        __syncthreads();
    }

    // epilogue: acc -> smem staging (stride 132) -> coalesced gmem + bias
    float* Cs = sm;
    #pragma unroll
    for (int mt = 0; mt < 2; mt++)
        #pragma unroll
        for (int nt = 0; nt < 8; nt++) {
            const int row = wm0 + mt * 16 + gid;
            const int col = wn0 + nt * 8 + tid4 * 2;
            Cs[row * 132 + col]           = acc[mt][nt][0];
            Cs[row * 132 + col + 1]       = acc[mt][nt][1];
            Cs[(row + 8) * 132 + col]     = acc[mt][nt][2];
            Cs[(row + 8) * 132 + col + 1] = acc[mt][nt][3];
        }
    __syncthreads();
    #pragma unroll
    for (int it = 0; it < 16; it++) {
        const int id  = tid + it * 256;
        const int row = id >> 5;
        const int c4  = (id & 31) * 4;
        float4 v = *reinterpret_cast<const float4*>(&Cs[row * 132 + c4]);
        const int gc = bx * 128 + c4;
        v.x += bias[gc + 0]; v.y += bias[gc + 1]; v.z += bias[gc + 2]; v.w += bias[gc + 3];
        *reinterpret_cast<float4*>(&C[(size_t)(by * 128 + row) * N + gc]) = v;
    }
}

// ======================= RoPE + scatter to (H, S, hd) ======================
__global__ void rope_scatter(const float* __restrict__ qkv,
                             const float* __restrict__ freqs,
                             float* __restrict__ Q, float* __restrict__ K,
                             float* __restrict__ V, int S)
{
    const int s = blockIdx.x;
    const float* base = qkv + (size_t)s * (3 * D_MODEL);
    for (int idx = threadIdx.x; idx < NHEADS * HDIM; idx += blockDim.x) {
        const int h = idx / HDIM;
        const int d = idx % HDIM;
        const int dd = (d < 40) ? d : d - 40;
        const float f  = freqs[(size_t)s * 40 + dd];
        const float cs = cosf(f), sn = sinf(f);
        const float q1 = base[h * HDIM + dd];
        const float q2 = base[h * HDIM + dd + 40];
        const float k1 = base[D_MODEL + h * HDIM + dd];
        const float k2 = base[D_MODEL + h * HDIM + dd + 40];
        const float qo = (d < 40) ? (q1 * cs - q2 * sn) : (q1 * sn + q2 * cs);
        const float ko = (d < 40) ? (k1 * cs - k2 * sn) : (k1 * sn + k2 * cs);
        const size_t o = ((size_t)h * S + s) * HDIM + d;
        Q[o] = qo;
        K[o] = ko;
        V[o] = base[2 * D_MODEL + h * HDIM + d];
    }
}

// ======================= attention: 128x128 tiles, 8x8 regs ================
// smem: Qt[80][128] Kt[80][128] Vs[128][84] Ss[128][132] alpha[128] lsum[128]
#define AT_SMEM ((80*128 + 80*128 + 128*84 + 128*132 + 128 + 128) * 4)

__global__ __launch_bounds__(256, 1)
void attn128(const float* __restrict__ Qg, const float* __restrict__ Kg,
             const float* __restrict__ Vg, const int* __restrict__ cu,
             int n_seg, float* __restrict__ out, int S)
{
    extern __shared__ float sma[];
    float* Qt    = sma;                   // [d][m]
    float* Kt    = Qt + 80 * 128;         // [d][n]
    float* Vs    = Kt + 80 * 128;         // [n][d] stride 84
    float* Ss    = Vs + 128 * 84;         // [m][n] stride 132
    float* alpha = Ss + 128 * 132;
    float* lsum  = alpha + 128;

    const int tid = threadIdx.x;
    const int h   = blockIdx.y;
    const int q0  = blockIdx.x * 128;

    int start = 0, end = S;
    for (int i = 0; i < n_seg; i++) {
        int a = cu[i], b = cu[i + 1];
        if (a <= q0 && q0 < b) { start = a; end = b; }
    }

    const int ty = tid >> 4, tx = tid & 15;
    const int srow = tid >> 1, shalf = tid & 1;
    const int lm = tid & 127, lh = tid >> 7;   // loader mapping

    // load Q transposed
    {
        const bool mv = (q0 + lm) < end;
        const float* Qrow = Qg + ((size_t)h * S + q0 + lm) * HDIM;
        #pragma unroll
        for (int it = 0; it < 10; it++) {
            const int d = (it * 2 + lh) * 4;
            float4 v = mv ? *reinterpret_cast<const float4*>(Qrow + d)
                          : make_float4(0.f, 0.f, 0.f, 0.f);
            Qt[(d + 0) * 128 + lm] = v.x;
            Qt[(d + 1) * 128 + lm] = v.y;
            Qt[(d + 2) * 128 + lm] = v.z;
            Qt[(d + 3) * 128 + lm] = v.w;
        }
    }

    float o[8][5];
    #pragma unroll
    for (int i = 0; i < 8; i++)
        #pragma unroll
        for (int j = 0; j < 5; j++) o[i][j] = 0.f;
    float m_run = -INFINITY, l_run = 0.f;
    const float scale = 0.11180339887498949f;   // 1/sqrt(80)

    const int nkt = (end - start + 127) / 128;
    for (int t = 0; t < nkt; t++) {
        const int k0 = start + t * 128;
        __syncthreads();
        // load K transposed + V natural
        {
            const bool mv = (k0 + lm) < end;
            const float* Krow = Kg + ((size_t)h * S + k0 + lm) * HDIM;
            const float* Vrow = Vg + ((size_t)h * S + k0 + lm) * HDIM;
            #pragma unroll
            for (int it = 0; it < 10; it++) {
                const int d = (it * 2 + lh) * 4;
                float4 kk = mv ? *reinterpret_cast<const float4*>(Krow + d)
                               : make_float4(0.f, 0.f, 0.f, 0.f);
                Kt[(d + 0) * 128 + lm] = kk.x;
                Kt[(d + 1) * 128 + lm] = kk.y;
                Kt[(d + 2) * 128 + lm] = kk.z;
                Kt[(d + 3) * 128 + lm] = kk.w;
                float4 vv = mv ? *reinterpret_cast<const float4*>(Vrow + d)
                               : make_float4(0.f, 0.f, 0.f, 0.f);
                *reinterpret_cast<float4*>(&Vs[lm * 84 + d]) = vv;
            }
        }
        __syncthreads();

        // ---- QK^T: 8x8 per thread over d=0..79 ----
        float acc[8][8];
        #pragma unroll
        for (int i = 0; i < 8; i++)
            #pragma unroll
            for (int j = 0; j < 8; j++) acc[i][j] = 0.f;
        const float4* Qt4 = reinterpret_cast<const float4*>(Qt);
        const float4* Kt4 = reinterpret_cast<const float4*>(Kt);
        #pragma unroll 4
        for (int d = 0; d < 80; d++) {
            float4 a0 = Qt4[d * 32 + ty * 2], a1 = Qt4[d * 32 + ty * 2 + 1];
            float4 b0 = Kt4[d * 32 + tx * 2], b1 = Kt4[d * 32 + tx * 2 + 1];
            float qa[8] = {a0.x, a0.y, a0.z, a0.w, a1.x, a1.y, a1.z, a1.w};
            float kb[8] = {b0.x, b0.y, b0.z, b0.w, b1.x, b1.y, b1.z, b1.w};
            #pragma unroll
            for (int i = 0; i < 8; i++)
                #pragma unroll
                for (int j = 0; j < 8; j++)
                    acc[i][j] += qa[i] * kb[j];
        }
        const int nv = end - k0;
        #pragma unroll
        for (int i = 0; i < 8; i++)
            #pragma unroll
            for (int j = 0; j < 8; j++) {
                const int c = tx * 8 + j;
                Ss[(ty * 8 + i) * 132 + c] = (c < nv) ? acc[i][j] * scale : -1e30f;
            }
        __syncthreads();

        // ---- online softmax: row srow, cols [shalf*64, +64) ----
        {
            float* Sr = Ss + srow * 132 + shalf * 64;
            float mt = -INFINITY;
            #pragma unroll
            for (int j4 = 0; j4 < 16; j4++) {
                float4 p = *reinterpret_cast<const float4*>(Sr + j4 * 4);
                mt = fmaxf(mt, fmaxf(fmaxf(p.x, p.y), fmaxf(p.z, p.w)));
            }
            mt = fmaxf(mt, __shfl_xor_sync(0xffffffffu, mt, 1));
            const float m_new = fmaxf(m_run, mt);
            const float al = __expf(m_run - m_new);
            float rs = 0.f;
            #pragma unroll
            for (int j4 = 0; j4 < 16; j4++) {
                float4 p = *reinterpret_cast<float4*>(Sr + j4 * 4);
                p.x = __expf(p.x - m_new); p.y = __expf(p.y - m_new);
                p.z = __expf(p.z - m_new); p.w = __expf(p.w - m_new);
                *reinterpret_cast<float4*>(Sr + j4 * 4) = p;
                rs += p.x + p.y + p.z + p.w;
            }
            rs += __shfl_xor_sync(0xffffffffu, rs, 1);
            l_run = l_run * al + rs;
            m_run = m_new;
            if (shalf == 0) alpha[srow] = al;
        }
        __syncthreads();

        // ---- PV: rows ty*8..+7, dims tx*5..+4 ----
        #pragma unroll
        for (int i = 0; i < 8; i++) {
            const float ai = alpha[ty * 8 + i];
            #pragma unroll
            for (int j = 0; j < 5; j++) o[i][j] *= ai;
        }
        #pragma unroll 2
        for (int c = 0; c < 128; c++) {
            float vr[5];
            #pragma unroll
            for (int j = 0; j < 5; j++) vr[j] = Vs[c * 84 + tx * 5 + j];
            #pragma unroll
            for (int i = 0; i < 8; i++) {
                const float p = Ss[(ty * 8 + i) * 132 + c];
                #pragma unroll
                for (int j = 0; j < 5; j++) o[i][j] += p * vr[j];
            }
        }
    }

    if (shalf == 0) lsum[srow] = l_run;
    __syncthreads();
    #pragma unroll
    for (int i = 0; i < 8; i++) {
        const int row = q0 + ty * 8 + i;
        if (row < end) {
            const float inv = 1.f / lsum[ty * 8 + i];
            #pragma unroll
            for (int j = 0; j < 5; j++)
                out[(size_t)row * D_MODEL + h * HDIM + tx * 5 + j] = o[i][j] * inv;
        }
    }
}

// ======================= launch ============================================
extern "C" void kernel_launch(void* const* d_in, const int* in_sizes, int n_in,
                              void* d_out, int out_size)
{
    const float* hidden = (const float*)d_in[0];
    const int*   cu     = (const int*)  d_in[1];
    const float* rope   = (const float*)d_in[2];
    const float* w_qkv  = (const float*)d_in[3];
    const float* b_qkv  = (const float*)d_in[4];
    const float* w_proj = (const float*)d_in[5];
    const float* b_proj = (const float*)d_in[6];
    float* out = (float*)d_out;

    const int S     = in_sizes[0] / D_MODEL;
    const int n_seg = in_sizes[1] - 1;

    float *qkv_p, *q_p, *k_p, *v_p, *attn_p, *wqkv_t, *wproj_t;
    cudaGetSymbolAddress((void**)&qkv_p,   g_qkv);
    cudaGetSymbolAddress((void**)&q_p,     g_q);
    cudaGetSymbolAddress((void**)&k_p,     g_k);
    cudaGetSymbolAddress((void**)&v_p,     g_v);
    cudaGetSymbolAddress((void**)&attn_p,  g_attn);
    cudaGetSymbolAddress((void**)&wqkv_t,  g_wqkv_t);
    cudaGetSymbolAddress((void**)&wproj_t, g_wproj_t);

    cudaFuncSetAttribute(gemm_tf32, cudaFuncAttributeMaxDynamicSharedMemorySize, GEMM_SMEM);
    cudaFuncSetAttribute(attn128,   cudaFuncAttributeMaxDynamicSharedMemorySize, AT_SMEM);

    // 0) transpose weights to K-major
    {
        dim3 blk(32, 8);
        transpose_kernel<<<dim3(3 * D_MODEL / 32, D_MODEL / 32), blk>>>(w_qkv, wqkv_t, D_MODEL, 3 * D_MODEL);
        transpose_kernel<<<dim3(D_MODEL / 32, D_MODEL / 32), blk>>>(w_proj, wproj_t, D_MODEL, D_MODEL);
    }

    // 1) QKV projection (tf32 mma.sync)
    gemm_tf32<<<dim3(3 * D_MODEL / 128, S / 128), 256, GEMM_SMEM>>>(
        hidden, wqkv_t, b_qkv, qkv_p, S, 3 * D_MODEL, D_MODEL);

    // 2) RoPE + scatter
    rope_scatter<<<S, 256>>>(qkv_p, rope, q_p, k_p, v_p, S);

    // 3) block-diagonal attention
    attn128<<<dim3(S / 128, NHEADS), 256, AT_SMEM>>>(q_p, k_p, v_p, cu, n_seg, attn_p, S);

    // 4) output projection (tf32 mma.sync)
    gemm_tf32<<<dim3(D_MODEL / 128, S / 128), 256, GEMM_SMEM>>>(
        attn_p, wproj_t, b_proj, out, S, D_MODEL, D_MODEL);
}

// round 4
// speedup vs baseline: 2.3213x; 1.2881x over previous
#include <cuda_runtime.h>
#include <math.h>
#include <cstdint>

#define D_MODEL 1280
#define NHEADS  16
#define HDIM    80
#define S_MAX   4096

// ---------------- scratch (device globals; no allocation allowed) ----------
__device__ float g_qkv[S_MAX * 3 * D_MODEL];
__device__ float g_q[NHEADS * S_MAX * HDIM];
__device__ float g_k[NHEADS * S_MAX * HDIM];
__device__ float g_v[NHEADS * S_MAX * HDIM];
__device__ float g_attn[S_MAX * D_MODEL];
__device__ float g_wqkv_t[3 * D_MODEL * D_MODEL];   // (3D, D) K-major
__device__ float g_wproj_t[D_MODEL * D_MODEL];      // (D, D) K-major

// ======================= helpers ===========================================
__device__ __forceinline__ uint32_t smem_u32(const void* p) {
    uint32_t a;
    asm("{ .reg .u64 t; cvta.to.shared.u64 t, %1; cvt.u32.u64 %0, t; }" : "=r"(a) : "l"(p));
    return a;
}
__device__ __forceinline__ void cp16(uint32_t dst, const void* src) {
    asm volatile("cp.async.cg.shared.global [%0], [%1], 16;" :: "r"(dst), "l"(src));
}
#define CP_COMMIT() asm volatile("cp.async.commit_group;" ::: "memory")
#define CP_WAIT(n)  asm volatile("cp.async.wait_group %0;" :: "n"(n) : "memory")

__device__ __forceinline__ uint32_t f2tf32(float x) {
    uint32_t r;
    asm("cvt.rna.tf32.f32 %0, %1;" : "=r"(r) : "f"(x));
    return r;
}
__device__ __forceinline__ float tf32f(float x) { return __uint_as_float(f2tf32(x)); }

__device__ __forceinline__ void mma_tf32(float* c, const uint32_t* a, const uint32_t* b) {
    asm volatile(
        "mma.sync.aligned.m16n8k8.row.col.f32.tf32.tf32.f32 "
        "{%0,%1,%2,%3}, {%4,%5,%6,%7}, {%8,%9}, {%0,%1,%2,%3};"
        : "+f"(c[0]), "+f"(c[1]), "+f"(c[2]), "+f"(c[3])
        : "r"(a[0]), "r"(a[1]), "r"(a[2]), "r"(a[3]), "r"(b[0]), "r"(b[1]));
}

// ======================= transpose (K,N) -> (N,K) ==========================
__global__ void transpose_kernel(const float* __restrict__ in, float* __restrict__ out,
                                 int K, int N) {
    __shared__ float tile[32][33];
    const int k0 = blockIdx.y * 32, n0 = blockIdx.x * 32;
    const int tx = threadIdx.x, ty = threadIdx.y;
    #pragma unroll
    for (int i = ty; i < 32; i += 8)
        tile[i][tx] = in[(size_t)(k0 + i) * N + n0 + tx];
    __syncthreads();
    #pragma unroll
    for (int i = ty; i < 32; i += 8)
        out[(size_t)(n0 + i) * K + k0 + tx] = tile[tx][i];
}

// ======================= tf32 mma.sync GEMM ================================
#define GSTR 36
#define GEMM_SMEM (2 * 2 * 128 * GSTR * 4)

__global__ __launch_bounds__(256, 1)
void gemm_tf32(const float* __restrict__ A, const float* __restrict__ Bt,
               const float* __restrict__ bias, float* __restrict__ C,
               int M, int N, int K)
{
    extern __shared__ float sm[];
    const int tid  = threadIdx.x;
    const int warp = tid >> 5, lane = tid & 31;
    const int gid  = lane >> 2, tid4 = lane & 3;
    const int wm0  = (warp & 3) * 32;
    const int wn0  = (warp >> 2) * 64;
    const int bx = blockIdx.x, by = blockIdx.y;

    const float* Ablk = A  + (size_t)by * 128 * K;
    const float* Bblk = Bt + (size_t)bx * 128 * K;
    const int NS = K / 32;
    const uint32_t sbase = smem_u32(sm);

    auto load_stage = [&](int b, int ks) {
        #pragma unroll
        for (int i = 0; i < 8; i++) {
            const int id  = tid + i * 256;
            const int isB = id >> 10;
            const int row = (id >> 3) & 127;
            const int c16 = id & 7;
            const float* src = (isB ? Bblk : Ablk) + (size_t)row * K + ks * 32 + c16 * 4;
            const uint32_t dst = sbase +
                (uint32_t)(b * (2 * 128 * GSTR) + isB * (128 * GSTR) + row * GSTR + c16 * 4) * 4u;
            cp16(dst, src);
        }
        CP_COMMIT();
    };

    float acc[2][8][4];
    #pragma unroll
    for (int mt = 0; mt < 2; mt++)
        #pragma unroll
        for (int nt = 0; nt < 8; nt++)
            #pragma unroll
            for (int r = 0; r < 4; r++) acc[mt][nt][r] = 0.f;

    load_stage(0, 0);
    for (int ks = 0; ks < NS; ks++) {
        const int b = ks & 1;
        if (ks + 1 < NS) { load_stage(1 - b, ks + 1); CP_WAIT(1); }
        else             { CP_WAIT(0); }
        __syncthreads();

        const float* As = sm + b * (2 * 128 * GSTR);
        const float* Bs = As + 128 * GSTR;

        #pragma unroll
        for (int kk = 0; kk < 4; kk++) {
            const int k0 = kk * 8;
            uint32_t af[2][4], bf[8][2];
            #pragma unroll
            for (int mt = 0; mt < 2; mt++) {
                const int r = (wm0 + mt * 16 + gid) * GSTR;
                af[mt][0] = f2tf32(As[r + k0 + tid4]);
                af[mt][1] = f2tf32(As[r + 8 * GSTR + k0 + tid4]);
                af[mt][2] = f2tf32(As[r + k0 + tid4 + 4]);
                af[mt][3] = f2tf32(As[r + 8 * GSTR + k0 + tid4 + 4]);
            }
            #pragma unroll
            for (int nt = 0; nt < 8; nt++) {
                const int r = (wn0 + nt * 8 + gid) * GSTR;
                bf[nt][0] = f2tf32(Bs[r + k0 + tid4]);
                bf[nt][1] = f2tf32(Bs[r + k0 + tid4 + 4]);
            }
            #pragma unroll
            for (int mt = 0; mt < 2; mt++)
                #pragma unroll
                for (int nt = 0; nt < 8; nt++)
                    mma_tf32(acc[mt][nt], af[mt], bf[nt]);
        }
        __syncthreads();
    }

    float* Cs = sm;
    #pragma unroll
    for (int mt = 0; mt < 2; mt++)
        #pragma unroll
        for (int nt = 0; nt < 8; nt++) {
            const int row = wm0 + mt * 16 + gid;
            const int col = wn0 + nt * 8 + tid4 * 2;
            Cs[row * 132 + col]           = acc[mt][nt][0];
            Cs[row * 132 + col + 1]       = acc[mt][nt][1];
            Cs[(row + 8) * 132 + col]     = acc[mt][nt][2];
            Cs[(row + 8) * 132 + col + 1] = acc[mt][nt][3];
        }
    __syncthreads();
    #pragma unroll
    for (int it = 0; it < 16; it++) {
        const int id  = tid + it * 256;
        const int row = id >> 5;
        const int c4  = (id & 31) * 4;
        float4 v = *reinterpret_cast<const float4*>(&Cs[row * 132 + c4]);
        const int gc = bx * 128 + c4;
        v.x += bias[gc + 0]; v.y += bias[gc + 1]; v.z += bias[gc + 2]; v.w += bias[gc + 3];
        *reinterpret_cast<float4*>(&C[(size_t)(by * 128 + row) * N + gc]) = v;
    }
}

// ======================= RoPE + scatter to (H, S, hd) ======================
__global__ void rope_scatter(const float* __restrict__ qkv,
                             const float* __restrict__ freqs,
                             float* __restrict__ Q, float* __restrict__ K,
                             float* __restrict__ V, int S)
{
    const int s = blockIdx.x;
    const float* base = qkv + (size_t)s * (3 * D_MODEL);
    for (int idx = threadIdx.x; idx < NHEADS * HDIM; idx += blockDim.x) {
        const int h = idx / HDIM;
        const int d = idx % HDIM;
        const int dd = (d < 40) ? d : d - 40;
        const float f  = freqs[(size_t)s * 40 + dd];
        const float cs = cosf(f), sn = sinf(f);
        const float q1 = base[h * HDIM + dd];
        const float q2 = base[h * HDIM + dd + 40];
        const float k1 = base[D_MODEL + h * HDIM + dd];
        const float k2 = base[D_MODEL + h * HDIM + dd + 40];
        const float qo = (d < 40) ? (q1 * cs - q2 * sn) : (q1 * sn + q2 * cs);
        const float ko = (d < 40) ? (k1 * cs - k2 * sn) : (k1 * sn + k2 * cs);
        const size_t o = ((size_t)h * S + s) * HDIM + d;
        Q[o] = qo;
        K[o] = ko;
        V[o] = base[2 * D_MODEL + h * HDIM + d];
    }
}

// ======================= tensor-core attention =============================
// CTA = (q-tile 128, head). 8 warps, warp tile = 16 q-rows x 64 keys.
// QK^T: full hi/lo split (3 MMAs). PV: V-side split (2 MMAs).
// smem (floats): Qh[128*84] Ql[128*84] Kh[64*84] Kl[64*84]
//                Vh_t[80*68] Vl_t[80*68] P[8*16*68]
#define ATC_FLOATS (2*128*84 + 2*64*84 + 2*80*68 + 8*16*68)
#define ATC_SMEM   (ATC_FLOATS * 4)

__global__ __launch_bounds__(256, 1)
void attn_tc(const float* __restrict__ Qg, const float* __restrict__ Kg,
             const float* __restrict__ Vg, const int* __restrict__ cu,
             int n_seg, float* __restrict__ out, int S)
{
    extern __shared__ float sm[];
    float* Qh = sm;
    float* Ql = Qh + 128 * 84;
    float* Kh = Ql + 128 * 84;
    float* Kl = Kh + 64 * 84;
    float* Vh = Kl + 64 * 84;     // transposed [hd][key], stride 68
    float* Vl = Vh + 80 * 68;
    float* Ps = Vl + 80 * 68;     // per-warp [16][68]

    const int tid  = threadIdx.x;
    const int warp = tid >> 5, lane = tid & 31;
    const int gid  = lane >> 2, tid4 = lane & 3;
    const int wq   = warp * 16;
    const int h    = blockIdx.y;
    const int q0   = blockIdx.x * 128;

    int start = 0, end = S;
    for (int i = 0; i < n_seg; i++) {
        int a = cu[i], b = cu[i + 1];
        if (a <= q0 && q0 < b) { start = a; end = b; }
    }

    const float scale = 0.11180339887498949f;   // 1/sqrt(80)

    // ---- load Q, scale, split hi/lo ----
    {
        const int r  = tid >> 1;
        const int cb = (tid & 1) * 40;
        const bool mv = (q0 + r) < end;
        const float* Qrow = Qg + ((size_t)h * S + q0 + r) * HDIM + cb;
        #pragma unroll
        for (int i = 0; i < 10; i++) {
            float4 v = mv ? *reinterpret_cast<const float4*>(Qrow + i * 4)
                          : make_float4(0.f, 0.f, 0.f, 0.f);
            float x[4] = {v.x * scale, v.y * scale, v.z * scale, v.w * scale};
            float4 hv, lv;
            float* hp = &hv.x; float* lp = &lv.x;
            #pragma unroll
            for (int j = 0; j < 4; j++) {
                float hi = tf32f(x[j]);
                hp[j] = hi;
                lp[j] = tf32f(x[j] - hi);
            }
            *reinterpret_cast<float4*>(&Qh[r * 84 + cb + i * 4]) = hv;
            *reinterpret_cast<float4*>(&Ql[r * 84 + cb + i * 4]) = lv;
        }
    }

    float acc_o[10][4];
    #pragma unroll
    for (int n = 0; n < 10; n++)
        #pragma unroll
        for (int r = 0; r < 4; r++) acc_o[n][r] = 0.f;
    float m0 = -INFINITY, m1 = -INFINITY, l0 = 0.f, l1 = 0.f;

    float* Pw = Ps + warp * 16 * 68;
    const int nkt = (end - start + 63) / 64;

    for (int t = 0; t < nkt; t++) {
        const int k0 = start + t * 64;
        __syncthreads();   // previous tile's smem consumers done

        // ---- load K (split, [key][hd]) and V (split, transposed [hd][key]) ----
        {
            const int r  = tid >> 2;
            const int cb = (tid & 3) * 20;
            const bool mv = (k0 + r) < end;
            const float* Krow = Kg + ((size_t)h * S + k0 + r) * HDIM + cb;
            const float* Vrow = Vg + ((size_t)h * S + k0 + r) * HDIM + cb;
            #pragma unroll
            for (int i = 0; i < 5; i++) {
                float4 kk = mv ? *reinterpret_cast<const float4*>(Krow + i * 4)
                               : make_float4(0.f, 0.f, 0.f, 0.f);
                float4 hv, lv;
                float* kp = &kk.x; float* hp = &hv.x; float* lp = &lv.x;
                #pragma unroll
                for (int j = 0; j < 4; j++) {
                    float hi = tf32f(kp[j]);
                    hp[j] = hi;
                    lp[j] = tf32f(kp[j] - hi);
                }
                *reinterpret_cast<float4*>(&Kh[r * 84 + cb + i * 4]) = hv;
                *reinterpret_cast<float4*>(&Kl[r * 84 + cb + i * 4]) = lv;

                float4 vv = mv ? *reinterpret_cast<const float4*>(Vrow + i * 4)
                               : make_float4(0.f, 0.f, 0.f, 0.f);
                float* vp = &vv.x;
                #pragma unroll
                for (int j = 0; j < 4; j++) {
                    float hi = tf32f(vp[j]);
                    Vh[(cb + i * 4 + j) * 68 + r] = hi;
                    Vl[(cb + i * 4 + j) * 68 + r] = tf32f(vp[j] - hi);
                }
            }
        }
        __syncthreads();

        // ---- QK^T (3-MMA split) ----
        float acc_s[8][4];
        #pragma unroll
        for (int n = 0; n < 8; n++)
            #pragma unroll
            for (int r = 0; r < 4; r++) acc_s[n][r] = 0.f;

        #pragma unroll
        for (int kk = 0; kk < 10; kk++) {
            const int k8 = kk * 8;
            uint32_t ah[4], al[4];
            ah[0] = __float_as_uint(Qh[(wq + gid)     * 84 + k8 + tid4]);
            ah[1] = __float_as_uint(Qh[(wq + gid + 8) * 84 + k8 + tid4]);
            ah[2] = __float_as_uint(Qh[(wq + gid)     * 84 + k8 + tid4 + 4]);
            ah[3] = __float_as_uint(Qh[(wq + gid + 8) * 84 + k8 + tid4 + 4]);
            al[0] = __float_as_uint(Ql[(wq + gid)     * 84 + k8 + tid4]);
            al[1] = __float_as_uint(Ql[(wq + gid + 8) * 84 + k8 + tid4]);
            al[2] = __float_as_uint(Ql[(wq + gid)     * 84 + k8 + tid4 + 4]);
            al[3] = __float_as_uint(Ql[(wq + gid + 8) * 84 + k8 + tid4 + 4]);
            #pragma unroll
            for (int nt = 0; nt < 8; nt++) {
                uint32_t bh[2], bl[2];
                bh[0] = __float_as_uint(Kh[(nt * 8 + gid) * 84 + k8 + tid4]);
                bh[1] = __float_as_uint(Kh[(nt * 8 + gid) * 84 + k8 + tid4 + 4]);
                bl[0] = __float_as_uint(Kl[(nt * 8 + gid) * 84 + k8 + tid4]);
                bl[1] = __float_as_uint(Kl[(nt * 8 + gid) * 84 + k8 + tid4 + 4]);
                mma_tf32(acc_s[nt], ah, bh);
                mma_tf32(acc_s[nt], al, bh);
                mma_tf32(acc_s[nt], ah, bl);
            }
        }

        // ---- mask + online softmax (rows fully warp-local) ----
        const int nv = end - k0;
        float mt0 = -INFINITY, mt1 = -INFINITY;
        #pragma unroll
        for (int nt = 0; nt < 8; nt++) {
            #pragma unroll
            for (int j = 0; j < 2; j++) {
                const int c = nt * 8 + 2 * tid4 + j;
                if (c >= nv) { acc_s[nt][j] = -1e30f; acc_s[nt][2 + j] = -1e30f; }
                mt0 = fmaxf(mt0, acc_s[nt][j]);
                mt1 = fmaxf(mt1, acc_s[nt][2 + j]);
            }
        }
        mt0 = fmaxf(mt0, __shfl_xor_sync(0xffffffffu, mt0, 1));
        mt0 = fmaxf(mt0, __shfl_xor_sync(0xffffffffu, mt0, 2));
        mt1 = fmaxf(mt1, __shfl_xor_sync(0xffffffffu, mt1, 1));
        mt1 = fmaxf(mt1, __shfl_xor_sync(0xffffffffu, mt1, 2));

        const float mn0 = fmaxf(m0, mt0), mn1 = fmaxf(m1, mt1);
        const float al0 = __expf(m0 - mn0), al1 = __expf(m1 - mn1);
        m0 = mn0; m1 = mn1;

        float rs0 = 0.f, rs1 = 0.f;
        #pragma unroll
        for (int nt = 0; nt < 8; nt++) {
            #pragma unroll
            for (int j = 0; j < 2; j++) {
                float p0 = __expf(acc_s[nt][j]     - m0);
                float p1 = __expf(acc_s[nt][2 + j] - m1);
                acc_s[nt][j]     = p0;
                acc_s[nt][2 + j] = p1;
                rs0 += p0; rs1 += p1;
            }
        }
        rs0 += __shfl_xor_sync(0xffffffffu, rs0, 1);
        rs0 += __shfl_xor_sync(0xffffffffu, rs0, 2);
        rs1 += __shfl_xor_sync(0xffffffffu, rs1, 1);
        rs1 += __shfl_xor_sync(0xffffffffu, rs1, 2);
        l0 = l0 * al0 + rs0;
        l1 = l1 * al1 + rs1;

        #pragma unroll
        for (int n = 0; n < 10; n++) {
            acc_o[n][0] *= al0; acc_o[n][1] *= al0;
            acc_o[n][2] *= al1; acc_o[n][3] *= al1;
        }

        // ---- store P (tf32-rounded) ----
        #pragma unroll
        for (int nt = 0; nt < 8; nt++) {
            float2 p0 = make_float2(tf32f(acc_s[nt][0]), tf32f(acc_s[nt][1]));
            float2 p1 = make_float2(tf32f(acc_s[nt][2]), tf32f(acc_s[nt][3]));
            *reinterpret_cast<float2*>(&Pw[gid       * 68 + nt * 8 + 2 * tid4]) = p0;
            *reinterpret_cast<float2*>(&Pw[(gid + 8) * 68 + nt * 8 + 2 * tid4]) = p1;
        }
        __syncwarp();

        // ---- PV (V-split, 2 MMAs) ----
        #pragma unroll
        for (int kk = 0; kk < 8; kk++) {
            const int k8 = kk * 8;
            uint32_t a[4];
            a[0] = __float_as_uint(Pw[gid       * 68 + k8 + tid4]);
            a[1] = __float_as_uint(Pw[(gid + 8) * 68 + k8 + tid4]);
            a[2] = __float_as_uint(Pw[gid       * 68 + k8 + tid4 + 4]);
            a[3] = __float_as_uint(Pw[(gid + 8) * 68 + k8 + tid4 + 4]);
            #pragma unroll
            for (int nt = 0; nt < 10; nt++) {
                uint32_t bh[2], bl[2];
                bh[0] = __float_as_uint(Vh[(nt * 8 + gid) * 68 + k8 + tid4]);
                bh[1] = __float_as_uint(Vh[(nt * 8 + gid) * 68 + k8 + tid4 + 4]);
                bl[0] = __float_as_uint(Vl[(nt * 8 + gid) * 68 + k8 + tid4]);
                bl[1] = __float_as_uint(Vl[(nt * 8 + gid) * 68 + k8 + tid4 + 4]);
                mma_tf32(acc_o[nt], a, bh);
                mma_tf32(acc_o[nt], a, bl);
            }
        }
    }

    // ---- epilogue ----
    const float inv0 = 1.f / l0, inv1 = 1.f / l1;
    const int r0 = q0 + wq + gid, r1 = r0 + 8;
    #pragma unroll
    for (int nt = 0; nt < 10; nt++) {
        const int col = h * HDIM + nt * 8 + 2 * tid4;
        if (r0 < end) {
            float2 v = make_float2(acc_o[nt][0] * inv0, acc_o[nt][1] * inv0);
            *reinterpret_cast<float2*>(&out[(size_t)r0 * D_MODEL + col]) = v;
        }
        if (r1 < end) {
            float2 v = make_float2(acc_o[nt][2] * inv1, acc_o[nt][3] * inv1);
            *reinterpret_cast<float2*>(&out[(size_t)r1 * D_MODEL + col]) = v;
        }
    }
}

// ======================= launch ============================================
extern "C" void kernel_launch(void* const* d_in, const int* in_sizes, int n_in,
                              void* d_out, int out_size)
{
    const float* hidden = (const float*)d_in[0];
    const int*   cu     = (const int*)  d_in[1];
    const float* rope   = (const float*)d_in[2];
    const float* w_qkv  = (const float*)d_in[3];
    const float* b_qkv  = (const float*)d_in[4];
    const float* w_proj = (const float*)d_in[5];
    const float* b_proj = (const float*)d_in[6];
    float* out = (float*)d_out;

    const int S     = in_sizes[0] / D_MODEL;
    const int n_seg = in_sizes[1] - 1;

    float *qkv_p, *q_p, *k_p, *v_p, *attn_p, *wqkv_t, *wproj_t;
    cudaGetSymbolAddress((void**)&qkv_p,   g_qkv);
    cudaGetSymbolAddress((void**)&q_p,     g_q);
    cudaGetSymbolAddress((void**)&k_p,     g_k);
    cudaGetSymbolAddress((void**)&v_p,     g_v);
    cudaGetSymbolAddress((void**)&attn_p,  g_attn);
    cudaGetSymbolAddress((void**)&wqkv_t,  g_wqkv_t);
    cudaGetSymbolAddress((void**)&wproj_t, g_wproj_t);

    cudaFuncSetAttribute(gemm_tf32, cudaFuncAttributeMaxDynamicSharedMemorySize, GEMM_SMEM);
    cudaFuncSetAttribute(attn_tc,   cudaFuncAttributeMaxDynamicSharedMemorySize, ATC_SMEM);

    // 0) transpose weights to K-major
    {
        dim3 blk(32, 8);
        transpose_kernel<<<dim3(3 * D_MODEL / 32, D_MODEL / 32), blk>>>(w_qkv, wqkv_t, D_MODEL, 3 * D_MODEL);
        transpose_kernel<<<dim3(D_MODEL / 32, D_MODEL / 32), blk>>>(w_proj, wproj_t, D_MODEL, D_MODEL);
    }

    // 1) QKV projection (tf32 mma.sync)
    gemm_tf32<<<dim3(3 * D_MODEL / 128, S / 128), 256, GEMM_SMEM>>>(
        hidden, wqkv_t, b_qkv, qkv_p, S, 3 * D_MODEL, D_MODEL);

    // 2) RoPE + scatter
    rope_scatter<<<S, 256>>>(qkv_p, rope, q_p, k_p, v_p, S);

    // 3) block-diagonal attention (tensor cores)
    attn_tc<<<dim3(S / 128, NHEADS), 256, ATC_SMEM>>>(q_p, k_p, v_p, cu, n_seg, attn_p, S);

    // 4) output projection (tf32 mma.sync)
    gemm_tf32<<<dim3(D_MODEL / 128, S / 128), 256, GEMM_SMEM>>>(
        attn_p, wproj_t, b_proj, out, S, D_MODEL, D_MODEL);
}